// round 11
// baseline (speedup 1.0000x reference)
#include <cuda_runtime.h>
#include <cuda_fp16.h>
#include <cstdint>

// Problem dims
#define B_    64
#define T_    512
#define V_    512
#define E_    128
#define IMG_  1024
#define H_    512
#define G4    2048   // 4*H

// Recurrent kernel partitioning
#define PODS  4      // batch groups (independent)
#define UBLK  32     // unit-blocks per pod
#define BPB   16     // batches per block
#define UPB   16     // hidden units per block
#define LROWS 64     // gate rows per block (4 gates * UPB)
#define NTHR  256
#define WPAD  520    // padded row stride (fp16 elems) -> 260 words, +4 banks/row
#define PPAD  68     // padded partials row stride (floats)
#define NREP  4      // counter replicas (poll-contention spreading)
#define HBUF  (B_ * H_)   // one h buffer (fp16 elems)

// Scratch (device globals; no allocation allowed)
__device__ float g_emb_proj[V_ * G4];   // 4 MB
__device__ float g_img_hat[B_ * G4];    // 512 KB
__device__ __half g_h[2 * HBUF];        // DOUBLE-BUFFERED by step parity
__device__ float g_hn[B_ * H_];
// replica r for (pod,t) at g_cnt[r*PODS*T + pod*T + t]  (replicas 8KB apart)
__device__ unsigned g_cnt[NREP * PODS * T_];

// ---------------------------------------------------------------------------
// Generic small GEMM: C[m][n] = sum_k A[m*lda+k] * Bm[n*ldb+k] (+bias0+bias1)
// ---------------------------------------------------------------------------
__global__ __launch_bounds__(256)
void gemm_tn(const float* __restrict__ A, int lda,
             const float* __restrict__ Bm, int ldb,
             const float* __restrict__ bias0, const float* __restrict__ bias1,
             float* __restrict__ C, int ldc, int K)
{
    __shared__ float As[32][33];
    __shared__ float Bs[32][33];
    const int tid = threadIdx.x;
    const int m0 = blockIdx.y * 32;
    const int n0 = blockIdx.x * 32;
    const int ty = tid >> 4, tx = tid & 15;
    const int li = tid >> 3;          // 0..31
    const int lk = (tid & 7) * 4;     // 0,4,...,28

    float acc00 = 0.f, acc01 = 0.f, acc10 = 0.f, acc11 = 0.f;

    for (int k0 = 0; k0 < K; k0 += 32) {
        float4 av = *(const float4*)(A  + (size_t)(m0 + li) * lda + k0 + lk);
        float4 bv = *(const float4*)(Bm + (size_t)(n0 + li) * ldb + k0 + lk);
        As[li][lk + 0] = av.x; As[li][lk + 1] = av.y;
        As[li][lk + 2] = av.z; As[li][lk + 3] = av.w;
        Bs[li][lk + 0] = bv.x; Bs[li][lk + 1] = bv.y;
        Bs[li][lk + 2] = bv.z; Bs[li][lk + 3] = bv.w;
        __syncthreads();
        #pragma unroll
        for (int kk = 0; kk < 32; ++kk) {
            float a0 = As[2 * ty][kk],     a1 = As[2 * ty + 1][kk];
            float b0 = Bs[2 * tx][kk],     b1 = Bs[2 * tx + 1][kk];
            acc00 += a0 * b0; acc01 += a0 * b1;
            acc10 += a1 * b0; acc11 += a1 * b1;
        }
        __syncthreads();
    }

    float bj0 = 0.f, bj1 = 0.f;
    if (bias0) { bj0 += bias0[n0 + 2 * tx]; bj1 += bias0[n0 + 2 * tx + 1]; }
    if (bias1) { bj0 += bias1[n0 + 2 * tx]; bj1 += bias1[n0 + 2 * tx + 1]; }

    C[(size_t)(m0 + 2 * ty)     * ldc + n0 + 2 * tx]     = acc00 + bj0;
    C[(size_t)(m0 + 2 * ty)     * ldc + n0 + 2 * tx + 1] = acc01 + bj1;
    C[(size_t)(m0 + 2 * ty + 1) * ldc + n0 + 2 * tx]     = acc10 + bj0;
    C[(size_t)(m0 + 2 * ty + 1) * ldc + n0 + 2 * tx + 1] = acc11 + bj1;
}

__global__ void zero_cnt_kernel() {
    int i = blockIdx.x * blockDim.x + threadIdx.x;
    if (i < NREP * PODS * T_) g_cnt[i] = 0u;
}

// ---------------------------------------------------------------------------
// fp16 warp MMA m16n8k16: D(f32) += A(f16) * B(f16)
// ---------------------------------------------------------------------------
__device__ __forceinline__ void mma16816(float& c0, float& c1, float& c2, float& c3,
                                         uint32_t a0, uint32_t a1, uint32_t a2, uint32_t a3,
                                         uint32_t b0, uint32_t b1)
{
    asm volatile(
        "mma.sync.aligned.m16n8k16.row.col.f32.f16.f16.f32 "
        "{%0,%1,%2,%3}, {%4,%5,%6,%7}, {%8,%9}, {%0,%1,%2,%3};"
        : "+f"(c0), "+f"(c1), "+f"(c2), "+f"(c3)
        : "r"(a0), "r"(a1), "r"(a2), "r"(a3), "r"(b0), "r"(b1));
}

__device__ __forceinline__ void ldmx4(uint32_t& r0, uint32_t& r1, uint32_t& r2, uint32_t& r3,
                                      uint32_t addr)
{
    asm volatile("ldmatrix.sync.aligned.m8n8.x4.shared.b16 {%0,%1,%2,%3}, [%4];"
                 : "=r"(r0), "=r"(r1), "=r"(r2), "=r"(r3) : "r"(addr));
}

__device__ __forceinline__ float sigmf(float x) {
    return __fdividef(1.f, 1.f + __expf(-x));
}
__device__ __forceinline__ float tanh_fast(float x) {
    float y;
    asm("tanh.approx.f32 %0, %1;" : "=f"(y) : "f"(x));
    return y;
}
__device__ __forceinline__ uint32_t smem_u32(const void* p) {
    return (uint32_t)__cvta_generic_to_shared(p);
}

// ---------------------------------------------------------------------------
// Persistent LSTM recurrence.
//  * g_h double-buffered by step parity: write buf[t&1], stage buf[t&1 ^ 1].
//    Arrival at step t certifies BOTH "h(t) written" and "h(t-1) reads done",
//    so producers can never overwrite a buffer a consumer is still reading.
//  * 4 replicated arrival counters per (pod,t): producers red all 4,
//    consumers poll replica (ug&3) -> 8 pollers/line instead of 32.
//  * pair-local staging: warp-pair kg stages its 4KB A-quarter, then
//    bar.sync(1+kg, 64) instead of a block-wide __syncthreads.
// ---------------------------------------------------------------------------
__global__ __launch_bounds__(NTHR, 1)
void lstm_kernel(const int* __restrict__ x2, const int* __restrict__ lens,
                 const float* __restrict__ Whh)
{
    extern __shared__ char smraw[];
    __half* whi = (__half*)smraw;                         // 64*WPAD (init; then tokens)
    __half* hsh = whi + LROWS * WPAD;                     // 16*WPAD
    float* part  = (float*)(hsh + BPB * WPAD);            // 4*16*PPAD
    float* imgsh = part + 4 * BPB * PPAD;                 // 16*64
    int*   lensh = (int*)(imgsh + BPB * LROWS);           // 16
    int*   toksh = (int*)whi;                             // aliases whi after init

    const int tid = threadIdx.x;
    const int pod = blockIdx.x / UBLK;
    const int ug  = blockIdx.x % UBLK;
    const int b0  = pod * BPB;
    const int u0  = ug * UPB;

    // --- W_hh slice: load fp32 -> fp16 in smem ---
    for (int idx = tid; idx < LROWS * H_; idx += NTHR) {
        int r = idx >> 9;          // /512
        int k = idx & 511;
        int q = r >> 4, ul = r & 15;
        whi[r * WPAD + k] =
            __float2half_rn(Whh[(size_t)(q * H_ + u0 + ul) * H_ + k]);
    }
    // img_hat slice (includes b_ih + b_hh)
    for (int idx = tid; idx < BPB * LROWS; idx += NTHR) {
        int b = idx >> 6, r = idx & 63;
        int q = r >> 4, ul = r & 15;
        imgsh[idx] = g_img_hat[(size_t)(b0 + b) * G4 + q * H_ + u0 + ul];
    }
    if (tid < BPB) lensh[tid] = lens[b0 + tid];
    __syncthreads();

    // identities
    const int gb = tid >> 4;   // 0..15 batch (gate phase)
    const int gu = tid & 15;   // 0..15 unit
    const int wid = tid >> 5;
    const int kg  = wid >> 1;       // 0..3  K-group of 128 (= A quarter)
    const int ng  = wid & 1;        // 0..1  N-group of 32 rows
    const int lane = tid & 31;
    const int g  = lane >> 2;       // 0..7
    const int tq = lane & 3;        // 0..3
    const int pl = ng * 32 + lane;  // 0..63 lane within warp pair

    const uint32_t* Wh = (const uint32_t*)whi;

    // --- Preload ALL W fragments into registers (held for entire t-loop) ---
    uint32_t bhf[64];
    #pragma unroll
    for (int j = 0; j < 8; ++j) {
        #pragma unroll
        for (int nt = 0; nt < 4; ++nt) {
            const int wr = (ng * 32 + nt * 8 + g) * 260 + kg * 64 + j * 8 + tq;
            bhf[(j * 4 + nt) * 2]     = Wh[wr];
            bhf[(j * 4 + nt) * 2 + 1] = Wh[wr + 4];
        }
    }
    __syncthreads();   // W smem now dead; reuse whi region for tokens

    // Cache this block's token rows in smem: toksh[b][t]
    for (int idx = tid; idx < BPB * T_; idx += NTHR) {
        int b = idx >> 9, t = idx & 511;
        toksh[idx] = x2[(size_t)(b0 + b) * T_ + t];
    }
    __syncthreads();

    // ldmatrix per-lane base address: row = lane&15, half = lane>>4 (16B)
    const uint32_t lm_base = smem_u32(hsh) + (lane & 15) * (WPAD * 2)
                             + ((lane >> 4) & 1) * 16 + kg * 256;

    unsigned* cnt0 = g_cnt + pod * T_;                      // replica 0
    const unsigned* mypoll = g_cnt + (ug & 3) * (PODS * T_) + pod * T_;
    float cstate = 0.f;

    for (int t = 0; t < T_; ++t) {
        // gx gather for this (batch, unit): issued early, consumed in gate phase
        int tok = toksh[gb * T_ + t];
        const float* ep = g_emb_proj + (size_t)tok * G4 + u0 + gu;
        float e0 = ep[0];
        float e1 = ep[H_];
        float e2 = ep[2 * H_];
        float e3 = ep[3 * H_];

        if (t > 0) {
            // --- wait for all pod blocks to publish h(t-1) (own replica) ---
            {
                const unsigned* cp = mypoll + (t - 1);
                unsigned v;
                do {
                    asm volatile("ld.acquire.gpu.global.u32 %0, [%1];"
                                 : "=r"(v) : "l"(cp));
                } while (v < UBLK);
            }
            // --- warp-pair kg stages its 4KB A-quarter (16 rows x 128 units)
            //     from the h(t-1) buffer (parity (t-1)&1 = (t&1)^1) ---
            {
                const uint4* srch =
                    (const uint4*)(g_h + (size_t)((t & 1) ^ 1) * HBUF);
                #pragma unroll
                for (int i = 0; i < 4; ++i) {
                    int idx = pl + i * 64;            // 0..255
                    int r = idx >> 4, c = idx & 15;   // row, 16B chunk in quarter
                    *(uint4*)((char*)hsh + r * (WPAD * 2) + kg * 256 + c * 16) =
                        srch[(size_t)(b0 + r) * 64 + kg * 16 + c];
                }
            }
            // pair-local barrier (2 warps, 64 threads)
            asm volatile("bar.sync %0, 64;" :: "r"(1 + kg) : "memory");

            // --- MMA phase: warp M16 x N32 x K128, single fp16 W ---
            float c0[4], c1[4], c2[4], c3[4];
            #pragma unroll
            for (int nt = 0; nt < 4; ++nt) { c0[nt] = c1[nt] = c2[nt] = c3[nt] = 0.f; }

            #pragma unroll
            for (int j = 0; j < 8; ++j) {
                uint32_t a0, a1, a2, a3;
                ldmx4(a0, a1, a2, a3, lm_base + j * 32);
                #pragma unroll
                for (int nt = 0; nt < 4; ++nt) {
                    mma16816(c0[nt], c1[nt], c2[nt], c3[nt], a0, a1, a2, a3,
                             bhf[(j * 4 + nt) * 2], bhf[(j * 4 + nt) * 2 + 1]);
                }
            }
            // --- write K-group partials (vectorized float2) ---
            float* pb = part + kg * (BPB * PPAD);
            #pragma unroll
            for (int nt = 0; nt < 4; ++nt) {
                int n = ng * 32 + nt * 8 + 2 * tq;
                *(float2*)&pb[g * PPAD + n]       = make_float2(c0[nt], c1[nt]);
                *(float2*)&pb[(g + 8) * PPAD + n] = make_float2(c2[nt], c3[nt]);
            }
            __syncthreads();
        }

        // --- gate phase: thread (gb, gu) ---
        float gI = e0 + imgsh[gb * LROWS + gu];
        float gF = e1 + imgsh[gb * LROWS + 16 + gu];
        float gG = e2 + imgsh[gb * LROWS + 32 + gu];
        float gO = e3 + imgsh[gb * LROWS + 48 + gu];
        if (t > 0) {
            #pragma unroll
            for (int kk = 0; kk < 4; ++kk) {
                const float* pp = part + kk * (BPB * PPAD) + gb * PPAD;
                gI += pp[gu];
                gF += pp[16 + gu];
                gG += pp[32 + gu];
                gO += pp[48 + gu];
            }
        }
        float iG = sigmf(gI);
        float fG = sigmf(gF);
        float gT = tanh_fast(gG);
        float oG = sigmf(gO);
        cstate = fG * cstate + iG * gT;
        float hval = oG * tanh_fast(cstate);

        // write h(t) into parity buffer t&1
        g_h[(size_t)(t & 1) * HBUF + (size_t)(b0 + gb) * H_ + u0 + gu] =
            __float2half_rn(hval);
        if (t == lensh[gb] - 1)
            g_hn[(size_t)(b0 + gb) * H_ + u0 + gu] = hval;

        // --- arrive: publish h(t) on all 4 counter replicas ---
        if (t < T_ - 1) {
            __syncthreads();          // all threads' h stores before the release
            if (tid == 0) {
                #pragma unroll
                for (int r = 0; r < NREP; ++r) {
                    asm volatile("red.release.gpu.global.add.u32 [%0], %1;"
                                 :: "l"(cnt0 + r * (PODS * T_) + t), "r"(1u)
                                 : "memory");
                }
            }
        }
    }
}

// ---------------------------------------------------------------------------
// Launch  (lstm is the 4th launch: the slot ncu -s 5 -c 1 lands on)
// ---------------------------------------------------------------------------
static const int LSTM_SMEM =
    (LROWS * WPAD + BPB * WPAD) * 2                       // whi + hsh (fp16)
    + (4 * BPB * PPAD + BPB * LROWS) * 4                  // part + imgsh
    + BPB * 4 + 16;

extern "C" void kernel_launch(void* const* d_in, const int* in_sizes, int n_in,
                              void* d_out, int out_size)
{
    (void)in_sizes; (void)n_in; (void)out_size;
    const float* x1    = (const float*)d_in[0];
    const int*   x2    = (const int*)  d_in[1];
    const int*   lens  = (const int*)  d_in[2];
    const float* emb   = (const float*)d_in[3];
    const float* W_ih  = (const float*)d_in[4];
    const float* W_hh  = (const float*)d_in[5];
    const float* b_ih  = (const float*)d_in[6];
    const float* b_hh  = (const float*)d_in[7];
    const float* W_act = (const float*)d_in[8];
    const float* b_act = (const float*)d_in[9];
    float* out = (float*)d_out;

    float *embp = nullptr, *imgp = nullptr, *hnp = nullptr;
    cudaGetSymbolAddress((void**)&embp, g_emb_proj);
    cudaGetSymbolAddress((void**)&imgp, g_img_hat);
    cudaGetSymbolAddress((void**)&hnp,  g_hn);

    cudaFuncSetAttribute(lstm_kernel,
                         cudaFuncAttributeMaxDynamicSharedMemorySize, LSTM_SMEM);

    // #1: emb_proj[V,4H] = emb @ W_ih[:,IMG:]^T
    gemm_tn<<<dim3(G4 / 32, V_ / 32), 256>>>(
        emb, E_, W_ih + IMG_, E_ + IMG_, nullptr, nullptr, embp, G4, E_);

    // #2: img_hat[B,4H] = x1 @ W_ih[:,:IMG]^T + b_ih + b_hh
    gemm_tn<<<dim3(G4 / 32, B_ / 32), 256>>>(
        x1, IMG_, W_ih, E_ + IMG_, b_ih, b_hh, imgp, G4, IMG_);

    // #3: zero barrier counters
    zero_cnt_kernel<<<(NREP * PODS * T_ + 255) / 256, 256>>>();

    // #4: recurrence (persistent, 128 co-resident blocks) — profiled slot
    lstm_kernel<<<PODS * UBLK, NTHR, LSTM_SMEM>>>(x2, lens, W_hh);

    // #5: action head: out[B,A] = hn @ W_act^T + b_act
    gemm_tn<<<dim3(512 / 32, B_ / 32), 256>>>(
        hnp, H_, W_act, H_, b_act, nullptr, out, 512, H_);
}

// round 12
// speedup vs baseline: 1.7332x; 1.7332x over previous
#include <cuda_runtime.h>
#include <cuda_fp16.h>
#include <cstdint>

// Problem dims
#define B_    64
#define T_    512
#define V_    512
#define E_    128
#define IMG_  1024
#define H_    512
#define G4    2048   // 4*H

// Recurrent kernel partitioning
#define PODS  4      // batch groups (independent)
#define UBLK  32     // unit-blocks per pod
#define BPB   16     // batches per block
#define UPB   16     // hidden units per block
#define LROWS 64     // gate rows per block (4 gates * UPB)
#define NTHR  256
#define WPAD  520    // padded row stride (fp16 elems) -> 260 words, +4 banks/row
#define PPAD  68     // padded partials row stride (floats)
#define HBUF  (B_ * H_)   // one h buffer (fp16 elems)

// Scratch (device globals; no allocation allowed)
__device__ float g_emb_proj[V_ * G4];   // 4 MB
__device__ float g_img_hat[B_ * G4];    // 512 KB
__device__ __half g_h[2 * HBUF];        // double-buffered by step parity
__device__ float g_hn[B_ * H_];
__device__ unsigned g_cnt[PODS * T_];   // per-step arrival counters

// ---------------------------------------------------------------------------
// Generic small GEMM: C[m][n] = sum_k A[m*lda+k] * Bm[n*ldb+k] (+bias0+bias1)
// ---------------------------------------------------------------------------
__global__ __launch_bounds__(256)
void gemm_tn(const float* __restrict__ A, int lda,
             const float* __restrict__ Bm, int ldb,
             const float* __restrict__ bias0, const float* __restrict__ bias1,
             float* __restrict__ C, int ldc, int K)
{
    __shared__ float As[32][33];
    __shared__ float Bs[32][33];
    const int tid = threadIdx.x;
    const int m0 = blockIdx.y * 32;
    const int n0 = blockIdx.x * 32;
    const int ty = tid >> 4, tx = tid & 15;
    const int li = tid >> 3;          // 0..31
    const int lk = (tid & 7) * 4;     // 0,4,...,28

    float acc00 = 0.f, acc01 = 0.f, acc10 = 0.f, acc11 = 0.f;

    for (int k0 = 0; k0 < K; k0 += 32) {
        float4 av = *(const float4*)(A  + (size_t)(m0 + li) * lda + k0 + lk);
        float4 bv = *(const float4*)(Bm + (size_t)(n0 + li) * ldb + k0 + lk);
        As[li][lk + 0] = av.x; As[li][lk + 1] = av.y;
        As[li][lk + 2] = av.z; As[li][lk + 3] = av.w;
        Bs[li][lk + 0] = bv.x; Bs[li][lk + 1] = bv.y;
        Bs[li][lk + 2] = bv.z; Bs[li][lk + 3] = bv.w;
        __syncthreads();
        #pragma unroll
        for (int kk = 0; kk < 32; ++kk) {
            float a0 = As[2 * ty][kk],     a1 = As[2 * ty + 1][kk];
            float b0 = Bs[2 * tx][kk],     b1 = Bs[2 * tx + 1][kk];
            acc00 += a0 * b0; acc01 += a0 * b1;
            acc10 += a1 * b0; acc11 += a1 * b1;
        }
        __syncthreads();
    }

    float bj0 = 0.f, bj1 = 0.f;
    if (bias0) { bj0 += bias0[n0 + 2 * tx]; bj1 += bias0[n0 + 2 * tx + 1]; }
    if (bias1) { bj0 += bias1[n0 + 2 * tx]; bj1 += bias1[n0 + 2 * tx + 1]; }

    C[(size_t)(m0 + 2 * ty)     * ldc + n0 + 2 * tx]     = acc00 + bj0;
    C[(size_t)(m0 + 2 * ty)     * ldc + n0 + 2 * tx + 1] = acc01 + bj1;
    C[(size_t)(m0 + 2 * ty + 1) * ldc + n0 + 2 * tx]     = acc10 + bj0;
    C[(size_t)(m0 + 2 * ty + 1) * ldc + n0 + 2 * tx + 1] = acc11 + bj1;
}

__global__ void zero_cnt_kernel() {
    int i = blockIdx.x * blockDim.x + threadIdx.x;
    if (i < PODS * T_) g_cnt[i] = 0u;
}

// ---------------------------------------------------------------------------
// fp16 warp MMA m16n8k16: D(f32) += A(f16) * B(f16)
// ---------------------------------------------------------------------------
__device__ __forceinline__ void mma16816(float& c0, float& c1, float& c2, float& c3,
                                         uint32_t a0, uint32_t a1, uint32_t a2, uint32_t a3,
                                         uint32_t b0, uint32_t b1)
{
    asm volatile(
        "mma.sync.aligned.m16n8k16.row.col.f32.f16.f16.f32 "
        "{%0,%1,%2,%3}, {%4,%5,%6,%7}, {%8,%9}, {%0,%1,%2,%3};"
        : "+f"(c0), "+f"(c1), "+f"(c2), "+f"(c3)
        : "r"(a0), "r"(a1), "r"(a2), "r"(a3), "r"(b0), "r"(b1));
}

__device__ __forceinline__ void ldmx4(uint32_t& r0, uint32_t& r1, uint32_t& r2, uint32_t& r3,
                                      uint32_t addr)
{
    asm volatile("ldmatrix.sync.aligned.m8n8.x4.shared.b16 {%0,%1,%2,%3}, [%4];"
                 : "=r"(r0), "=r"(r1), "=r"(r2), "=r"(r3) : "r"(addr));
}

__device__ __forceinline__ float sigmf(float x) {
    return __fdividef(1.f, 1.f + __expf(-x));
}
__device__ __forceinline__ float tanh_fast(float x) {
    float y;
    asm("tanh.approx.f32 %0, %1;" : "=f"(y) : "f"(x));
    return y;
}
__device__ __forceinline__ uint32_t smem_u32(const void* p) {
    return (uint32_t)__cvta_generic_to_shared(p);
}

// ---------------------------------------------------------------------------
// Persistent LSTM recurrence — R9 monolithic skeleton + parity double buffer.
//  * write h(t) -> buf[t&1]; stage h(t-1) from buf[(t&1)^1].
//    Producer overwrites buf[p] at step t+2 only after cnt[t+1]==32, and every
//    consumer arrives at cnt[t+1] after its staging reads of buf[p] -> WAR
//    closed with zero extra sync.
//  * block-monolithic 256-thread staging, single counter per (pod,t),
//    single red.release arrival (fragmented variants measured slower:
//    R7 2039us, R11 1644us vs R9 1120us).
// ---------------------------------------------------------------------------
__global__ __launch_bounds__(NTHR, 1)
void lstm_kernel(const int* __restrict__ x2, const int* __restrict__ lens,
                 const float* __restrict__ Whh)
{
    extern __shared__ char smraw[];
    __half* whi = (__half*)smraw;                         // 64*WPAD (init; then tokens)
    __half* hsh = whi + LROWS * WPAD;                     // 16*WPAD
    float* part  = (float*)(hsh + BPB * WPAD);            // 4*16*PPAD
    float* imgsh = part + 4 * BPB * PPAD;                 // 16*64
    int*   lensh = (int*)(imgsh + BPB * LROWS);           // 16
    int*   toksh = (int*)whi;                             // aliases whi after init

    const int tid = threadIdx.x;
    const int pod = blockIdx.x / UBLK;
    const int ug  = blockIdx.x % UBLK;
    const int b0  = pod * BPB;
    const int u0  = ug * UPB;

    // --- W_hh slice: load fp32 -> fp16 in smem ---
    for (int idx = tid; idx < LROWS * H_; idx += NTHR) {
        int r = idx >> 9;          // /512
        int k = idx & 511;
        int q = r >> 4, ul = r & 15;
        whi[r * WPAD + k] =
            __float2half_rn(Whh[(size_t)(q * H_ + u0 + ul) * H_ + k]);
    }
    // img_hat slice (includes b_ih + b_hh)
    for (int idx = tid; idx < BPB * LROWS; idx += NTHR) {
        int b = idx >> 6, r = idx & 63;
        int q = r >> 4, ul = r & 15;
        imgsh[idx] = g_img_hat[(size_t)(b0 + b) * G4 + q * H_ + u0 + ul];
    }
    if (tid < BPB) lensh[tid] = lens[b0 + tid];
    __syncthreads();

    // identities
    const int gb = tid >> 4;   // 0..15 batch (gate phase)
    const int gu = tid & 15;   // 0..15 unit
    const int wid = tid >> 5;
    const int kg  = wid >> 1;       // 0..3  K-group of 128
    const int ng  = wid & 1;        // 0..1  N-group of 32 rows
    const int lane = tid & 31;
    const int g  = lane >> 2;       // 0..7
    const int tq = lane & 3;        // 0..3

    const uint32_t* Wh = (const uint32_t*)whi;

    // --- Preload ALL W fragments into registers (held for entire t-loop) ---
    uint32_t bhf[64];
    #pragma unroll
    for (int j = 0; j < 8; ++j) {
        #pragma unroll
        for (int nt = 0; nt < 4; ++nt) {
            const int wr = (ng * 32 + nt * 8 + g) * 260 + kg * 64 + j * 8 + tq;
            bhf[(j * 4 + nt) * 2]     = Wh[wr];
            bhf[(j * 4 + nt) * 2 + 1] = Wh[wr + 4];
        }
    }
    __syncthreads();   // W smem now dead; reuse whi region for tokens

    // Cache this block's token rows in smem: toksh[b][t]
    for (int idx = tid; idx < BPB * T_; idx += NTHR) {
        int b = idx >> 9, t = idx & 511;
        toksh[idx] = x2[(size_t)(b0 + b) * T_ + t];
    }
    __syncthreads();

    // ldmatrix per-lane base address: row = lane&15, half = lane>>4 (16B)
    const uint32_t lm_base = smem_u32(hsh) + (lane & 15) * (WPAD * 2)
                             + ((lane >> 4) & 1) * 16 + kg * 256;

    volatile unsigned* cnt = g_cnt + pod * T_;
    float cstate = 0.f;

    for (int t = 0; t < T_; ++t) {
        // gx gather for this (batch, unit): issued early, consumed in gate phase
        int tok = toksh[gb * T_ + t];
        const float* ep = g_emb_proj + (size_t)tok * G4 + u0 + gu;
        float e0 = ep[0];
        float e1 = ep[H_];
        float e2 = ep[2 * H_];
        float e3 = ep[3 * H_];

        if (t > 0) {
            // --- wait for all pod blocks to publish h(t-1) ---
            {
                const unsigned* cp = (const unsigned*)&cnt[t - 1];
                unsigned v;
                do {
                    asm volatile("ld.acquire.gpu.global.u32 %0, [%1];"
                                 : "=r"(v) : "l"(cp));
                } while (v < UBLK);
            }
            // --- stage h(t-1) slice [16][512] fp16 into smem (block-wide) ---
            {
                const uint4* srch =
                    (const uint4*)(g_h + (size_t)((t & 1) ^ 1) * HBUF);
                #pragma unroll
                for (int i = 0; i < 4; ++i) {
                    int idx = tid + i * NTHR;        // 0..1023
                    int r = idx >> 6, c = idx & 63;  // row, 16B-chunk
                    *(uint4*)((char*)hsh + r * (WPAD * 2) + c * 16) =
                        srch[(size_t)(b0 + r) * 64 + c];
                }
            }
            __syncthreads();

            // --- MMA phase: warp M16 x N32 x K128, single fp16 W ---
            float c0[4], c1[4], c2[4], c3[4];
            #pragma unroll
            for (int nt = 0; nt < 4; ++nt) { c0[nt] = c1[nt] = c2[nt] = c3[nt] = 0.f; }

            #pragma unroll
            for (int j = 0; j < 8; ++j) {
                uint32_t a0, a1, a2, a3;
                ldmx4(a0, a1, a2, a3, lm_base + j * 32);
                #pragma unroll
                for (int nt = 0; nt < 4; ++nt) {
                    mma16816(c0[nt], c1[nt], c2[nt], c3[nt], a0, a1, a2, a3,
                             bhf[(j * 4 + nt) * 2], bhf[(j * 4 + nt) * 2 + 1]);
                }
            }
            // --- write K-group partials (vectorized float2) ---
            float* pb = part + kg * (BPB * PPAD);
            #pragma unroll
            for (int nt = 0; nt < 4; ++nt) {
                int n = ng * 32 + nt * 8 + 2 * tq;
                *(float2*)&pb[g * PPAD + n]       = make_float2(c0[nt], c1[nt]);
                *(float2*)&pb[(g + 8) * PPAD + n] = make_float2(c2[nt], c3[nt]);
            }
            __syncthreads();
        }

        // --- gate phase: thread (gb, gu) ---
        float gI = e0 + imgsh[gb * LROWS + gu];
        float gF = e1 + imgsh[gb * LROWS + 16 + gu];
        float gG = e2 + imgsh[gb * LROWS + 32 + gu];
        float gO = e3 + imgsh[gb * LROWS + 48 + gu];
        if (t > 0) {
            #pragma unroll
            for (int kk = 0; kk < 4; ++kk) {
                const float* pp = part + kk * (BPB * PPAD) + gb * PPAD;
                gI += pp[gu];
                gF += pp[16 + gu];
                gG += pp[32 + gu];
                gO += pp[48 + gu];
            }
        }
        float iG = sigmf(gI);
        float fG = sigmf(gF);
        float gT = tanh_fast(gG);
        float oG = sigmf(gO);
        cstate = fG * cstate + iG * gT;
        float hval = oG * tanh_fast(cstate);

        // write h(t) into parity buffer t&1
        g_h[(size_t)(t & 1) * HBUF + (size_t)(b0 + gb) * H_ + u0 + gu] =
            __float2half_rn(hval);
        if (t == lensh[gb] - 1)
            g_hn[(size_t)(b0 + gb) * H_ + u0 + gu] = hval;

        // --- arrive: publish h(t) for the pod ---
        if (t < T_ - 1) {
            __syncthreads();          // all threads' h stores before the release
            if (tid == 0) {
                asm volatile("red.release.gpu.global.add.u32 [%0], %1;"
                             :: "l"((unsigned*)&cnt[t]), "r"(1u) : "memory");
            }
        }
    }
}

// ---------------------------------------------------------------------------
// Launch  (lstm is the 4th launch: the slot ncu -s 5 -c 1 lands on)
// ---------------------------------------------------------------------------
static const int LSTM_SMEM =
    (LROWS * WPAD + BPB * WPAD) * 2                       // whi + hsh (fp16)
    + (4 * BPB * PPAD + BPB * LROWS) * 4                  // part + imgsh
    + BPB * 4 + 16;

extern "C" void kernel_launch(void* const* d_in, const int* in_sizes, int n_in,
                              void* d_out, int out_size)
{
    (void)in_sizes; (void)n_in; (void)out_size;
    const float* x1    = (const float*)d_in[0];
    const int*   x2    = (const int*)  d_in[1];
    const int*   lens  = (const int*)  d_in[2];
    const float* emb   = (const float*)d_in[3];
    const float* W_ih  = (const float*)d_in[4];
    const float* W_hh  = (const float*)d_in[5];
    const float* b_ih  = (const float*)d_in[6];
    const float* b_hh  = (const float*)d_in[7];
    const float* W_act = (const float*)d_in[8];
    const float* b_act = (const float*)d_in[9];
    float* out = (float*)d_out;

    float *embp = nullptr, *imgp = nullptr, *hnp = nullptr;
    cudaGetSymbolAddress((void**)&embp, g_emb_proj);
    cudaGetSymbolAddress((void**)&imgp, g_img_hat);
    cudaGetSymbolAddress((void**)&hnp,  g_hn);

    cudaFuncSetAttribute(lstm_kernel,
                         cudaFuncAttributeMaxDynamicSharedMemorySize, LSTM_SMEM);

    // #1: emb_proj[V,4H] = emb @ W_ih[:,IMG:]^T
    gemm_tn<<<dim3(G4 / 32, V_ / 32), 256>>>(
        emb, E_, W_ih + IMG_, E_ + IMG_, nullptr, nullptr, embp, G4, E_);

    // #2: img_hat[B,4H] = x1 @ W_ih[:,:IMG]^T + b_ih + b_hh
    gemm_tn<<<dim3(G4 / 32, B_ / 32), 256>>>(
        x1, IMG_, W_ih, E_ + IMG_, b_ih, b_hh, imgp, G4, IMG_);

    // #3: zero barrier counters
    zero_cnt_kernel<<<(PODS * T_ + 255) / 256, 256>>>();

    // #4: recurrence (persistent, 128 co-resident blocks) — profiled slot
    lstm_kernel<<<PODS * UBLK, NTHR, LSTM_SMEM>>>(x2, lens, W_hh);

    // #5: action head: out[B,A] = hn @ W_act^T + b_act
    gemm_tn<<<dim3(512 / 32, B_ / 32), 256>>>(
        hnp, H_, W_act, H_, b_act, nullptr, out, 512, H_);
}